// round 2
// baseline (speedup 1.0000x reference)
#include <cuda_runtime.h>

// Problem constants (LocalCosineSimilarity): lhs (B,N1,DIM), rhs (B,NTOT,DIM)
// Output = [ sim(B,N1,NTOT) , lhs_norm(B,N1) ] concatenated, fp32.
// Only sim[b][i][f*N + i + 1] survives masking; everything else is -1e9.
#define BB   4
#define NN1  1024
#define DIM  1024
#define FF   4
#define NFRM 1025          // N = N1 + 1
#define NTOT 4100          // FF * NFRM = 4100 = 4 * 1025 (divisible by 4!)
#define NEGV -1e9f

__global__ __launch_bounds__(256, 8)
void lcs_kernel(const float* __restrict__ lhs,
                const float* __restrict__ rhs,
                float* __restrict__ out,
                long long norm_off)
{
    const int row = blockIdx.x;          // 0 .. B*N1-1
    const int b   = row >> 10;           // N1 = 1024
    const int i   = row & 1023;
    const int t   = threadIdx.x;

    // ---- load lhs float4 (256 threads x 4 floats = 1024) ----
    const float4* lrow = reinterpret_cast<const float4*>(lhs + (size_t)row * DIM);
    const float4 l = lrow[t];
    float lsq = l.x*l.x + l.y*l.y + l.z*l.z + l.w*l.w;

    // ---- 4 kept rhs rows: m = b*NTOT + f*NFRM + i + 1 ----
    float dot[FF], rsq[FF];
#pragma unroll
    for (int f = 0; f < FF; ++f) {
        const float4* rrow = reinterpret_cast<const float4*>(
            rhs + ((size_t)b * NTOT + (size_t)f * NFRM + i + 1) * DIM);
        const float4 r = rrow[t];
        dot[f] = l.x*r.x + l.y*r.y + l.z*r.z + l.w*r.w;
        rsq[f] = r.x*r.x + r.y*r.y + r.z*r.z + r.w*r.w;
    }

    // ---- warp reduce the 9 partials ----
#pragma unroll
    for (int o = 16; o > 0; o >>= 1) {
        lsq += __shfl_xor_sync(0xffffffffu, lsq, o);
#pragma unroll
        for (int f = 0; f < FF; ++f) {
            dot[f] += __shfl_xor_sync(0xffffffffu, dot[f], o);
            rsq[f] += __shfl_xor_sync(0xffffffffu, rsq[f], o);
        }
    }

    __shared__ float s[9][8];
    const int warp = t >> 5, lane = t & 31;
    if (lane == 0) {
        s[0][warp] = lsq;
#pragma unroll
        for (int f = 0; f < FF; ++f) { s[1+f][warp] = dot[f]; s[5+f][warp] = rsq[f]; }
    }

    // ---- stream -1e9 into this output row (exactly 1025 float4 = 4100 floats) ----
    float4* orow = reinterpret_cast<float4*>(out + (size_t)row * NTOT);
    const float4 neg4 = make_float4(NEGV, NEGV, NEGV, NEGV);
#pragma unroll
    for (int k = t; k < NTOT / 4; k += 256)     // k < 1025 — NO overrun
        orow[k] = neg4;

    __syncthreads();

    // ---- threads 0..3 finalize the 4 kept values; thread 0 writes the norm ----
    if (t < FF) {
        float Lsq = 0.f, D = 0.f, R = 0.f;
#pragma unroll
        for (int w = 0; w < 8; ++w) {
            Lsq += s[0][w];
            D   += s[1+t][w];
            R   += s[5+t][w];
        }
        const float c = D * rsqrtf(Lsq) * rsqrtf(R);
        out[(size_t)row * NTOT + (size_t)t * NFRM + i + 1] = c * c;
        if (t == 0)
            out[norm_off + row] = sqrtf(Lsq);
    }
}

extern "C" void kernel_launch(void* const* d_in, const int* in_sizes, int n_in,
                              void* d_out, int out_size)
{
    const float* lhs = (const float*)d_in[0];
    const float* rhs = (const float*)d_in[1];
    float* out = (float*)d_out;

    // lhs_norm tail lives in the last B*N1 elements of the output buffer.
    const long long norm_off = (long long)out_size - (long long)BB * NN1;

    lcs_kernel<<<BB * NN1, 256>>>(lhs, rhs, out, norm_off);
}

// round 3
// speedup vs baseline: 1.0026x; 1.0026x over previous
#include <cuda_runtime.h>

// LocalCosineSimilarity: lhs (B,N1,DIM), rhs (B,NTOT,DIM)
// Output = [ sim(B,N1,NTOT) , lhs_norm(B,N1) ] fp32.
// Only sim[b][i][f*N + i + 1] survives masking; rest is -1e9.
#define BB   4
#define NN1  1024
#define DIM  1024
#define FF   4
#define NFRM 1025          // N = N1 + 1
#define NTOT 4100          // FF * NFRM = 4 * 1025
#define NEGV -1e9f

__global__ __launch_bounds__(256, 6)
void lcs_kernel(const float* __restrict__ lhs,
                const float* __restrict__ rhs,
                float* __restrict__ out,
                long long norm_off)
{
    const int row = blockIdx.x;          // 0 .. B*N1-1
    const int b   = row >> 10;           // N1 = 1024
    const int i   = row & 1023;
    const int t   = threadIdx.x;

    // ---- Phase 1: issue ALL loads first (MLP = 5 per thread) ----
    const float4 l = __ldcs(reinterpret_cast<const float4*>(lhs + (size_t)row * DIM) + t);

    float4 r[FF];
#pragma unroll
    for (int f = 0; f < FF; ++f)
        r[f] = __ldcs(reinterpret_cast<const float4*>(
                   rhs + ((size_t)b * NTOT + (size_t)f * NFRM + i + 1) * DIM) + t);

    // ---- Phase 2: independent fill stores hide the load latency ----
    // Exactly 1025 float4 = 4100 floats per row; no overrun.
    float4* orow = reinterpret_cast<float4*>(out + (size_t)row * NTOT);
    const float4 neg4 = make_float4(NEGV, NEGV, NEGV, NEGV);
    orow[t]       = neg4;
    orow[t + 256] = neg4;
    orow[t + 512] = neg4;
    orow[t + 768] = neg4;
    if (t == 0) orow[1024] = neg4;

    // ---- Phase 3: consume loads ----
    float lsq = l.x*l.x + l.y*l.y + l.z*l.z + l.w*l.w;
    float dot[FF], rsq[FF];
#pragma unroll
    for (int f = 0; f < FF; ++f) {
        dot[f] = l.x*r[f].x + l.y*r[f].y + l.z*r[f].z + l.w*r[f].w;
        rsq[f] = r[f].x*r[f].x + r[f].y*r[f].y + r[f].z*r[f].z + r[f].w*r[f].w;
    }

    // ---- warp reduce 9 partials ----
#pragma unroll
    for (int o = 16; o > 0; o >>= 1) {
        lsq += __shfl_xor_sync(0xffffffffu, lsq, o);
#pragma unroll
        for (int f = 0; f < FF; ++f) {
            dot[f] += __shfl_xor_sync(0xffffffffu, dot[f], o);
            rsq[f] += __shfl_xor_sync(0xffffffffu, rsq[f], o);
        }
    }

    __shared__ float s[9][8];
    const int warp = t >> 5, lane = t & 31;
    if (lane == 0) {
        s[0][warp] = lsq;
#pragma unroll
        for (int f = 0; f < FF; ++f) { s[1+f][warp] = dot[f]; s[5+f][warp] = rsq[f]; }
    }
    __syncthreads();

    // ---- threads 0..3 finalize kept values; thread 0 writes the norm ----
    if (t < FF) {
        float Lsq = 0.f, D = 0.f, R = 0.f;
#pragma unroll
        for (int w = 0; w < 8; ++w) {
            Lsq += s[0][w];
            D   += s[1+t][w];
            R   += s[5+t][w];
        }
        const float c = D * rsqrtf(Lsq) * rsqrtf(R);
        out[(size_t)row * NTOT + (size_t)t * NFRM + i + 1] = c * c;
        if (t == 0)
            out[norm_off + row] = sqrtf(Lsq);
    }
}

extern "C" void kernel_launch(void* const* d_in, const int* in_sizes, int n_in,
                              void* d_out, int out_size)
{
    const float* lhs = (const float*)d_in[0];
    const float* rhs = (const float*)d_in[1];
    float* out = (float*)d_out;

    const long long norm_off = (long long)out_size - (long long)BB * NN1;

    lcs_kernel<<<BB * NN1, 256>>>(lhs, rhs, out, norm_off);
}